// round 6
// baseline (speedup 1.0000x reference)
#include <cuda_runtime.h>
#include <cstdint>

// out = mean( (box9(pred) - box9(target))^2 ), zero-padded on H,W.
// box9(pred)-box9(target) = box9(pred-target); separable 9x9 box.
//
// cp.async.bulk (TMA) streams raw pred/target rows into a 4-slot smem ring
// (2 full-width rows per slot, per tensor). Consumers: 4 warps x 128 cols;
// each thread owns 4 cols; diff + horizontal 9-sum via shuffles; vertical
// 9-sum as a register ring; square+accumulate. No LDG, minimal smem.

#define Wd      512
#define Hd      512
#define TH      32
#define NSTRIP  16
#define NIMG    64
#define NBLK    (NSTRIP * NIMG)       // 1024
#define GR      2                     // rows per group
#define NGRP    20                    // 40 input rows / 2
#define SLOTS   4
#define ROWB    2048                  // bytes per row (512 f32)
#define NTOT    16777216.0

// dynamic smem: pbuf[SLOTS][GR][512] | tbuf[SLOTS][GR][512] | 4 mbarriers
#define PT_FLOATS (SLOTS * GR * Wd)       // 4096
#define BAR_OFF   (2 * PT_FLOATS * 4)     // 32768 bytes
#define SMEM_BYTES (BAR_OFF + 64)

__device__ double       g_sum  = 0.0;
__device__ unsigned int g_done = 0;

static __device__ __forceinline__ uint32_t s2u(const void* p) {
    uint32_t a;
    asm("{ .reg .u64 t; cvta.to.shared.u64 t, %1; cvt.u32.u64 %0, t; }"
        : "=r"(a) : "l"(p));
    return a;
}
static __device__ __forceinline__ void mbar_init(uint32_t mb, uint32_t cnt) {
    asm volatile("mbarrier.init.shared.b64 [%0], %1;" :: "r"(mb), "r"(cnt) : "memory");
}
static __device__ __forceinline__ void mbar_expect_tx(uint32_t mb, uint32_t bytes) {
    asm volatile("mbarrier.arrive.expect_tx.shared.b64 _, [%0], %1;"
                 :: "r"(mb), "r"(bytes) : "memory");
}
static __device__ __forceinline__ void bulk_g2s(uint32_t dst, const void* src,
                                                uint32_t bytes, uint32_t mb) {
    asm volatile(
        "cp.async.bulk.shared::cta.global.mbarrier::complete_tx::bytes [%0], [%1], %2, [%3];"
        :: "r"(dst), "l"(src), "r"(bytes), "r"(mb) : "memory");
}
static __device__ __forceinline__ void mbar_wait(uint32_t mb, uint32_t parity) {
    asm volatile(
        "{\n\t"
        ".reg .pred P1;\n\t"
        "WL_%=:\n\t"
        "mbarrier.try_wait.parity.acquire.cta.shared::cta.b64 P1, [%0], %1, 0x989680;\n\t"
        "@P1 bra.uni WD_%=;\n\t"
        "bra.uni WL_%=;\n\t"
        "WD_%=:\n\t"
        "}"
        :: "r"(mb), "r"(parity) : "memory");
}

// issue group G's bulk copies (rows y0-4+GR*G .. +GR-1, clamped to [0,Hd))
static __device__ __forceinline__ void issue_group(
    int G, int y0, const float* pimg, const float* timg,
    uint32_t pbuf_u32, uint32_t tbuf_u32, uint32_t bar_u32)
{
    const int rbase = y0 - 4 + GR * G;
    int i0 = rbase < 0 ? -rbase : 0;
    int i1 = (rbase + GR > Hd) ? (Hd - rbase) : GR;
    if (i1 < i0) i1 = i0;
    const int n = i1 - i0;
    const int slot = G % SLOTS;
    const uint32_t mb = bar_u32 + slot * 8;
    mbar_expect_tx(mb, (uint32_t)(n * ROWB * 2));
    if (n > 0) {
        const uint32_t off = (uint32_t)(slot * GR + i0) * ROWB;
        const size_t gofs = (size_t)(rbase + i0) * Wd;
        bulk_g2s(pbuf_u32 + off, pimg + gofs, (uint32_t)(n * ROWB), mb);
        bulk_g2s(tbuf_u32 + off, timg + gofs, (uint32_t)(n * ROWB), mb);
    }
}

__global__ __launch_bounds__(128)
void pooled_mse_kernel(const float* __restrict__ pred,
                       const float* __restrict__ target,
                       float* __restrict__ out) {
    extern __shared__ float sm[];
    float* pbuf = sm;                       // [SLOTS][GR][512]
    float* tbuf = sm + PT_FLOATS;
    __shared__ float s_red[4];

    const uint32_t sbase    = s2u(sm);
    const uint32_t pbuf_u32 = sbase;
    const uint32_t tbuf_u32 = sbase + PT_FLOATS * 4;
    const uint32_t bar_u32  = sbase + BAR_OFF;

    const int tid  = threadIdx.x;
    const int lane = tid & 31;
    const int y0   = blockIdx.x * TH;
    const int img  = blockIdx.y;
    const int x0   = tid << 2;              // 4 cols per thread

    const float* pimg = pred   + (size_t)img * (Hd * Wd);
    const float* timg = target + (size_t)img * (Hd * Wd);

    if (tid == 0) {
        #pragma unroll
        for (int s = 0; s < SLOTS; s++) mbar_init(bar_u32 + s * 8, 1);
    }
    __syncthreads();
    if (tid == 0) {
        #pragma unroll
        for (int s = 0; s < SLOTS; s++)
            issue_group(s, y0, pimg, timg, pbuf_u32, tbuf_u32, bar_u32);
    }

    float4 Hring[9];
    float4 vs = make_float4(0.f, 0.f, 0.f, 0.f);
    float  acc = 0.0f;

    #pragma unroll
    for (int g = 0; g < NGRP; g++) {
        const int slot = g & (SLOTS - 1);
        mbar_wait(bar_u32 + slot * 8, (uint32_t)((g >> 2) & 1));

        #pragma unroll
        for (int i = 0; i < GR; i++) {
            const int r    = g * GR + i;         // 0..39 compile-time
            const int rabs = y0 - 4 + r;
            const bool valid = ((unsigned)rabs < (unsigned)Hd);

            const float* prow = pbuf + (slot * GR + i) * Wd;
            const float* trow = tbuf + (slot * GR + i) * Wd;

            float4 d = make_float4(0.f, 0.f, 0.f, 0.f);
            if (valid) {
                const float4 p = *(const float4*)(prow + x0);
                const float4 t = *(const float4*)(trow + x0);
                d = make_float4(p.x - t.x, p.y - t.y, p.z - t.z, p.w - t.w);
            }

            float4 dl, dr;
            dl.x = __shfl_up_sync(0xFFFFFFFFu, d.x, 1);
            dl.y = __shfl_up_sync(0xFFFFFFFFu, d.y, 1);
            dl.z = __shfl_up_sync(0xFFFFFFFFu, d.z, 1);
            dl.w = __shfl_up_sync(0xFFFFFFFFu, d.w, 1);
            dr.x = __shfl_down_sync(0xFFFFFFFFu, d.x, 1);
            dr.y = __shfl_down_sync(0xFFFFFFFFu, d.y, 1);
            dr.z = __shfl_down_sync(0xFFFFFFFFu, d.z, 1);
            dr.w = __shfl_down_sync(0xFFFFFFFFu, d.w, 1);
            if (lane == 0) {                      // cross-warp / image-left halo
                dl = make_float4(0.f, 0.f, 0.f, 0.f);
                if (valid && x0 != 0) {
                    const float4 p = *(const float4*)(prow + x0 - 4);
                    const float4 t = *(const float4*)(trow + x0 - 4);
                    dl = make_float4(p.x - t.x, p.y - t.y, p.z - t.z, p.w - t.w);
                }
            }
            if (lane == 31) {                     // cross-warp / image-right halo
                dr = make_float4(0.f, 0.f, 0.f, 0.f);
                if (valid && x0 != Wd - 4) {
                    const float4 p = *(const float4*)(prow + x0 + 4);
                    const float4 t = *(const float4*)(trow + x0 + 4);
                    dr = make_float4(p.x - t.x, p.y - t.y, p.z - t.z, p.w - t.w);
                }
            }

            const float h0 = ((dl.x + dl.y) + (dl.z + dl.w))
                           + ((d.x + d.y) + (d.z + d.w)) + dr.x;
            const float h1 = h0 - dl.x + dr.y;
            const float h2 = h1 - dl.y + dr.z;
            const float h3 = h2 - dl.z + dr.w;
            Hring[r % 9] = make_float4(h0, h1, h2, h3);

            vs.x += h0; vs.y += h1; vs.z += h2; vs.w += h3;
            if (r >= 8) {
                acc += vs.x * vs.x + vs.y * vs.y + vs.z * vs.z + vs.w * vs.w;
                const float4 ho = Hring[(r - 8) % 9];
                vs.x -= ho.x; vs.y -= ho.y; vs.z -= ho.z; vs.w -= ho.w;
            }
        }
        __syncthreads();                          // slot drained by all warps
        if (g + SLOTS < NGRP && tid == 0)
            issue_group(g + SLOTS, y0, pimg, timg, pbuf_u32, tbuf_u32, bar_u32);
    }

    // ---- block reduction (128 threads) ----
    #pragma unroll
    for (int off = 16; off > 0; off >>= 1)
        acc += __shfl_xor_sync(0xFFFFFFFFu, acc, off);
    const int warp = tid >> 5;
    if (lane == 0) s_red[warp] = acc;
    __syncthreads();
    if (warp == 0) {
        float v = (lane < 4) ? s_red[lane] : 0.0f;
        v += __shfl_xor_sync(0xFFFFFFFFu, v, 2);
        v += __shfl_xor_sync(0xFFFFFFFFu, v, 1);
        if (lane == 0) {
            atomicAdd(&g_sum, (double)v);
            __threadfence();
            const unsigned old = atomicAdd(&g_done, 1u);
            if (old == NBLK - 1) {
                const double s = *((volatile double*)&g_sum);
                out[0] = (float)(s / (81.0 * 81.0) / NTOT);
                g_sum  = 0.0;                     // reset for next graph replay
                g_done = 0u;
            }
        }
    }
}

extern "C" void kernel_launch(void* const* d_in, const int* in_sizes, int n_in,
                              void* d_out, int out_size) {
    const float* pred   = (const float*)d_in[0];
    const float* target = (const float*)d_in[1];
    float* out = (float*)d_out;
    cudaFuncSetAttribute(pooled_mse_kernel,
                         cudaFuncAttributeMaxDynamicSharedMemorySize, SMEM_BYTES);
    dim3 grid(NSTRIP, NIMG);                      // 1024 blocks
    pooled_mse_kernel<<<grid, 128, SMEM_BYTES>>>(pred, target, out);
}